// round 5
// baseline (speedup 1.0000x reference)
#include <cuda_runtime.h>
#include <cstddef>

// Fused axial attention on a 7x7 grid (N=512, Cq=64, Cv=512).
// out[n,c,h,w] = sum_j p[n,h,w,j]   * vH[(n*7+w), c, j]
//             + sum_y p[n,h,w,7+y] * vW[(n*7+h), c, y]
// p = softmax over 14 of [eH (diag-masked, transposed), eW].
//
// One kernel. Block = (c-chunk of 256, n). Each block recomputes the (tiny)
// logits+softmax for its n, then does the PV contraction with v held in
// REGISTERS (thread = channel): p reads are warp-uniform broadcasts, v reads
// are 98 conflict-free scalar LDS per thread, outputs bounce through smem so
// the global store is perfectly contiguous.

#define NEGV   (-1e20f)
#define CHUNK  256
#define CPAD   261            // odd -> stride-261 LDS walks all 32 banks

// q/k staging strides (both == 4 mod 32 -> bank-spread)
#define ASTRIDE 484
#define RSTRIDE 68

// shared layout (floats)
#define VBUF_OFF  0            // 49*CPAD = 12789 ; aliases q/k staging
#define QS_OFF    0            // 7*ASTRIDE = 3388
#define KT_OFF    3388         // 7*ASTRIDE = 3388 (ends 6776 < 12789)
#define PH_OFF    12792        // 49*8
#define PW_OFF    13184        // 49*8
#define LG_OFF    13576        // 49*14
#define SMEM_FLOATS 14262
#define SMEM_BYTES (SMEM_FLOATS * 4)

__global__ __launch_bounds__(256, 2) void axattn_fused(
    const float* __restrict__ qH, const float* __restrict__ kH,
    const float* __restrict__ vH,
    const float* __restrict__ qW, const float* __restrict__ kW,
    const float* __restrict__ vW,
    float* __restrict__ out, int Cv)
{
    extern __shared__ float smem[];
    float* vbuf = smem + VBUF_OFF;
    float* qs   = smem + QS_OFF;
    float* kt   = smem + KT_OFF;
    float* pHs  = smem + PH_OFF;
    float* pWs  = smem + PW_OFF;
    float* lg   = smem + LG_OFF;

    const int n   = blockIdx.y;
    const int c0  = blockIdx.x * CHUNK;
    const int tid = threadIdx.x;

    // ------------------------------------------------------------------
    // Logits (two passes: H then W), then softmax. Duplicated per c-chunk.
    // ------------------------------------------------------------------
    #pragma unroll
    for (int pass = 0; pass < 2; pass++) {
        const float* qsrc = (pass == 0 ? qH : qW) + (size_t)n * 3136;
        const float* ksrc = (pass == 0 ? kH : kW) + (size_t)n * 3136;

        if (pass == 1) __syncthreads();

        for (int i = tid; i < 3136; i += 256) {
            int a = i / 448, r = i % 448, row = r / 64, c = r % 64;
            qs[a * ASTRIDE + row * RSTRIDE + c] = qsrc[i];
        }
        for (int i = tid; i < 3136; i += 256) {
            int a = i / 448, r = i % 448, c = r / 7, j = r % 7;
            kt[a * ASTRIDE + j * RSTRIDE + c] = ksrc[i];
        }
        __syncthreads();

        for (int t = tid; t < 343; t += 256) {
            int h = t / 49, rem = t % 49, w = rem / 7, j = rem % 7;
            int a   = pass == 0 ? w : h;
            int row = pass == 0 ? h : w;
            const float4* q4 = (const float4*)(qs + a * ASTRIDE + row * RSTRIDE);
            const float4* k4 = (const float4*)(kt + a * ASTRIDE + j   * RSTRIDE);
            float4 acc4 = make_float4(0.f, 0.f, 0.f, 0.f);
            #pragma unroll
            for (int kk = 0; kk < 16; kk++) {
                float4 x = q4[kk], y = k4[kk];
                acc4.x += x.x * y.x; acc4.y += x.y * y.y;
                acc4.z += x.z * y.z; acc4.w += x.w * y.w;
            }
            float v = (acc4.x + acc4.y) + (acc4.z + acc4.w);
            if (pass == 0) lg[(h * 7 + w) * 14 + j]     = (h == j) ? NEGV : v;
            else           lg[(h * 7 + w) * 14 + 7 + j] = v;
        }
    }
    __syncthreads();

    if (tid < 49) {
        const float* row = lg + tid * 14;
        float m = row[0];
        #pragma unroll
        for (int s = 1; s < 14; s++) m = fmaxf(m, row[s]);
        float e[14];
        float sum = 0.f;
        #pragma unroll
        for (int s = 0; s < 14; s++) { e[s] = __expf(row[s] - m); sum += e[s]; }
        float inv = 1.f / sum;
        #pragma unroll
        for (int s = 0; s < 7; s++) {
            pHs[tid * 8 + s] = e[s]     * inv;
            pWs[tid * 8 + s] = e[s + 7] * inv;
        }
        pHs[tid * 8 + 7] = 0.f;
        pWs[tid * 8 + 7] = 0.f;
    }
    __syncthreads();

    // ------------------------------------------------------------------
    // Stage vH chunk into vbuf as [w][j][c], load to registers.
    // ------------------------------------------------------------------
    const size_t vrow = (size_t)Cv * 7;         // stride between b-slices
    {
        const float* src = vH + (size_t)n * 7 * vrow + (size_t)c0 * 7;
        for (int i = tid; i < 3136; i += 256) {
            int w  = i / 448;
            int r4 = (i % 448) * 4;
            float4 a = *(const float4*)(src + (size_t)w * vrow + r4);
            float va[4] = {a.x, a.y, a.z, a.w};
            #pragma unroll
            for (int t = 0; t < 4; t++) {
                int r = r4 + t, c = r / 7, j = r % 7;
                vbuf[(w * 7 + j) * CPAD + c] = va[t];
            }
        }
    }
    __syncthreads();

    float vh[7][7];
    #pragma unroll
    for (int w = 0; w < 7; w++)
        #pragma unroll
        for (int j = 0; j < 7; j++)
            vh[w][j] = vbuf[(w * 7 + j) * CPAD + tid];
    __syncthreads();

    // Stage vW over the same buffer; H-stage FMAs run under the LDG latency.
    {
        const float* src = vW + (size_t)n * 7 * vrow + (size_t)c0 * 7;
        for (int i = tid; i < 3136; i += 256) {
            int w  = i / 448;
            int r4 = (i % 448) * 4;
            float4 a = *(const float4*)(src + (size_t)w * vrow + r4);
            float va[4] = {a.x, a.y, a.z, a.w};
            #pragma unroll
            for (int t = 0; t < 4; t++) {
                int r = r4 + t, c = r / 7, j = r % 7;
                vbuf[(w * 7 + j) * CPAD + c] = va[t];
            }
        }
    }

    // H stage: acc[h][w] = sum_j pH[h,w,j] * vh[w][j]  (p = uniform broadcast)
    float acc[7][7];
    #pragma unroll
    for (int h = 0; h < 7; h++)
        #pragma unroll
        for (int w = 0; w < 7; w++) {
            const float4 p0 = *(const float4*)(pHs + (h * 7 + w) * 8);
            const float4 p1 = *(const float4*)(pHs + (h * 7 + w) * 8 + 4);
            acc[h][w] = p0.x * vh[w][0] + p0.y * vh[w][1] + p0.z * vh[w][2]
                      + p0.w * vh[w][3] + p1.x * vh[w][4] + p1.y * vh[w][5]
                      + p1.z * vh[w][6];
        }
    __syncthreads();

    float vw[7][7];
    #pragma unroll
    for (int w = 0; w < 7; w++)
        #pragma unroll
        for (int j = 0; j < 7; j++)
            vw[w][j] = vbuf[(w * 7 + j) * CPAD + tid];
    __syncthreads();          // vbuf free after this -> reused for out staging

    // W stage: acc[h][w] += sum_y pW[h,w,y] * vw[h][y]
    #pragma unroll
    for (int h = 0; h < 7; h++)
        #pragma unroll
        for (int w = 0; w < 7; w++) {
            const float4 p0 = *(const float4*)(pWs + (h * 7 + w) * 8);
            const float4 p1 = *(const float4*)(pWs + (h * 7 + w) * 8 + 4);
            acc[h][w] += p0.x * vw[h][0] + p0.y * vw[h][1] + p0.z * vw[h][2]
                       + p0.w * vw[h][3] + p1.x * vw[h][4] + p1.y * vw[h][5]
                       + p1.z * vw[h][6];
        }

    // Bounce to smem [hw][c] (STS: lanes = consecutive c -> conflict-free),
    // then contiguous global store.
    #pragma unroll
    for (int h = 0; h < 7; h++)
        #pragma unroll
        for (int w = 0; w < 7; w++)
            vbuf[(h * 7 + w) * CPAD + tid] = acc[h][w];
    __syncthreads();

    {
        float* ob = out + ((size_t)n * Cv + c0) * 49;
        int c  = tid / 49;
        int hw = tid - c * 49;
        for (int i = tid; i < CHUNK * 49; i += 256) {
            ob[i] = vbuf[hw * CPAD + c];        // stride-261 read: bank-clean
            hw += 11; c += 5;                   // 256 = 5*49 + 11
            if (hw >= 49) { hw -= 49; c += 1; }
        }
    }
}

extern "C" void kernel_launch(void* const* d_in, const int* in_sizes, int n_in,
                              void* d_out, int out_size)
{
    const float* qH = (const float*)d_in[0];
    const float* kH = (const float*)d_in[1];
    const float* vH = (const float*)d_in[2];
    const float* qW = (const float*)d_in[3];
    const float* kW = (const float*)d_in[4];
    const float* vW = (const float*)d_in[5];

    int N  = in_sizes[0] / (49 * 64);
    int Cv = in_sizes[2] / (N * 49);

    static bool attr_done = false;
    if (!attr_done) {
        cudaFuncSetAttribute(axattn_fused,
                             cudaFuncAttributeMaxDynamicSharedMemorySize,
                             SMEM_BYTES);
        attr_done = true;
    }

    dim3 grid((Cv + CHUNK - 1) / CHUNK, N);
    axattn_fused<<<grid, 256, SMEM_BYTES>>>(qH, kH, vH, qW, kW, vW,
                                            (float*)d_out, Cv);
}

// round 6
// speedup vs baseline: 1.8406x; 1.8406x over previous
#include <cuda_runtime.h>
#include <cstddef>

// Axial attention on a 7x7 grid (N=512, Cq=64, Cv=512).
// out[n,c,h,w] = sum_j p[n,h,w,j]   * vH[(n*7+w), c, j]
//             + sum_y p[n,h,w,7+y] * vW[(n*7+h), c, y]
// p = softmax over 14 of [eH (diag-masked, transposed), eW].

#define NEGV (-1e20f)
#define MAXN 1024

// raw logits scratch: lg[n][h*7+w][14]  ([0:7) = H slot, [7:14) = W slot)
__device__ float g_lg[(size_t)MAXN * 49 * 14];

// ---------------------------------------------------------------------------
// Kernel A: raw logits. Block = (n, pass). pass 0 = H, pass 1 = W.
// q staged as [a][row][c], k transposed to [a][j][c]; pads keep banks spread.
// ---------------------------------------------------------------------------
#define ASTRIDE 484   // slice stride (floats), %32 == 4
#define RSTRIDE 68    // row   stride (floats), %32 == 4

__global__ __launch_bounds__(384) void ax_logits(
    const float* __restrict__ qH, const float* __restrict__ kH,
    const float* __restrict__ qW, const float* __restrict__ kW)
{
    __shared__ float qs[7 * ASTRIDE];
    __shared__ float kt[7 * ASTRIDE];

    const int n    = blockIdx.x;
    const int pass = blockIdx.y;
    const int tid  = threadIdx.x;

    const float* qsrc = (pass ? qW : qH) + (size_t)n * 3136;
    const float* ksrc = (pass ? kW : kH) + (size_t)n * 3136;

    for (int i = tid; i < 3136; i += 384) {
        int a = i / 448, r = i % 448, row = r / 64, c = r % 64;
        qs[a * ASTRIDE + row * RSTRIDE + c] = qsrc[i];
    }
    for (int i = tid; i < 3136; i += 384) {
        int a = i / 448, r = i % 448, c = r / 7, j = r % 7;
        kt[a * ASTRIDE + j * RSTRIDE + c] = ksrc[i];
    }
    __syncthreads();

    if (tid < 343) {
        int h = tid / 49, rem = tid % 49, w = rem / 7, j = rem % 7;
        int a   = pass ? h : w;
        int row = pass ? w : h;
        const float4* q4 = (const float4*)(qs + a * ASTRIDE + row * RSTRIDE);
        const float4* k4 = (const float4*)(kt + a * ASTRIDE + j   * RSTRIDE);
        float4 s = make_float4(0.f, 0.f, 0.f, 0.f);
        #pragma unroll
        for (int kk = 0; kk < 16; kk++) {
            float4 x = q4[kk], y = k4[kk];
            s.x += x.x * y.x; s.y += x.y * y.y;
            s.z += x.z * y.z; s.w += x.w * y.w;
        }
        float v = (s.x + s.y) + (s.z + s.w);
        if (pass == 0 && h == j) v = NEGV;
        g_lg[(size_t)n * 686 + (size_t)(h * 7 + w) * 14 + pass * 7 + j] = v;
    }
}

// ---------------------------------------------------------------------------
// Kernel B: softmax (tiny, per block) + PV contraction with v in REGISTERS.
// Thread = channel (c0 + tid). v loads: 7 contiguous floats per (slice) at
// base + c*7 -> warp reads 896 contiguous bytes, fully coalesced, no repack.
// p reads are warp-uniform LDS.128 broadcasts. Output bounces through smem
// (aliased over the p/logit area) for coalesced STG.
// ---------------------------------------------------------------------------
#define CHUNK 256
#define CPAD2 257                 // odd stride -> conflict-free bounce
#define PH_OFF 704                // after lg[686] (16B aligned)
#define PW_OFF 1104               // after pHs[49*8] (16B aligned)
#define SMEMB_FLOATS (49 * CPAD2) // 12593 ; bounce aliases everything
#define SMEMB_BYTES (SMEMB_FLOATS * 4)

__global__ __launch_bounds__(256, 3) void ax_pv(
    const float* __restrict__ vH, const float* __restrict__ vW,
    float* __restrict__ out, int Cv)
{
    extern __shared__ float smem[];
    float* lg  = smem;
    float* pHs = smem + PH_OFF;
    float* pWs = smem + PW_OFF;

    const int n   = blockIdx.y;
    const int c0  = blockIdx.x * CHUNK;
    const int tid = threadIdx.x;
    const int c   = c0 + tid;

    {
        const float* gl = g_lg + (size_t)n * 686;
        for (int i = tid; i < 686; i += 256) lg[i] = gl[i];
    }
    __syncthreads();

    if (tid < 49) {
        const float* row = lg + tid * 14;
        float m = row[0];
        #pragma unroll
        for (int s = 1; s < 14; s++) m = fmaxf(m, row[s]);
        float e[14];
        float sum = 0.f;
        #pragma unroll
        for (int s = 0; s < 14; s++) { e[s] = __expf(row[s] - m); sum += e[s]; }
        float inv = 1.f / sum;
        #pragma unroll
        for (int s = 0; s < 7; s++) {
            pHs[tid * 8 + s] = e[s]     * inv;
            pWs[tid * 8 + s] = e[s + 7] * inv;
        }
        pHs[tid * 8 + 7] = 0.f;
        pWs[tid * 8 + 7] = 0.f;
    }
    __syncthreads();

    const size_t bstr = (size_t)Cv * 7;                // b-slice stride
    const float* vhp = vH + (size_t)n * 7 * bstr + (size_t)c * 7;
    const float* vwp = vW + (size_t)n * 7 * bstr + (size_t)c * 7;

    float acc[49];

    // H stage: acc[h*7+w] = sum_j pH[h,w,j] * vH[w][c][j]
    #pragma unroll
    for (int w = 0; w < 7; w++) {
        const float* vp = vhp + (size_t)w * bstr;
        float v0 = vp[0], v1 = vp[1], v2 = vp[2], v3 = vp[3],
              v4 = vp[4], v5 = vp[5], v6 = vp[6];
        #pragma unroll
        for (int h = 0; h < 7; h++) {
            const float4 p0 = *(const float4*)(pHs + (h * 7 + w) * 8);
            const float4 p1 = *(const float4*)(pHs + (h * 7 + w) * 8 + 4);
            acc[h * 7 + w] = p0.x * v0 + p0.y * v1 + p0.z * v2 + p0.w * v3
                           + p1.x * v4 + p1.y * v5 + p1.z * v6;
        }
    }

    // W stage: acc[h*7+w] += sum_y pW[h,w,y] * vW[h][c][y]
    #pragma unroll
    for (int h = 0; h < 7; h++) {
        const float* vp = vwp + (size_t)h * bstr;
        float v0 = vp[0], v1 = vp[1], v2 = vp[2], v3 = vp[3],
              v4 = vp[4], v5 = vp[5], v6 = vp[6];
        #pragma unroll
        for (int w = 0; w < 7; w++) {
            const float4 p0 = *(const float4*)(pWs + (h * 7 + w) * 8);
            const float4 p1 = *(const float4*)(pWs + (h * 7 + w) * 8 + 4);
            acc[h * 7 + w] += p0.x * v0 + p0.y * v1 + p0.z * v2 + p0.w * v3
                            + p1.x * v4 + p1.y * v5 + p1.z * v6;
        }
    }

    __syncthreads();   // everyone done reading pHs/pWs before bounce overwrite

    // Bounce [hw][c] (STS conflict-free: lanes = consecutive c), coalesced STG.
    #pragma unroll
    for (int hw = 0; hw < 49; hw++) smem[hw * CPAD2 + tid] = acc[hw];
    __syncthreads();

    {
        float* ob = out + ((size_t)n * Cv + c0) * 49;
        int cc = tid / 49;
        int hw = tid - cc * 49;
        for (int i = tid; i < CHUNK * 49; i += 256) {
            ob[i] = smem[hw * CPAD2 + cc];
            hw += 11; cc += 5;                 // 256 = 5*49 + 11
            if (hw >= 49) { hw -= 49; cc += 1; }
        }
    }
}

extern "C" void kernel_launch(void* const* d_in, const int* in_sizes, int n_in,
                              void* d_out, int out_size)
{
    const float* qH = (const float*)d_in[0];
    const float* kH = (const float*)d_in[1];
    const float* vH = (const float*)d_in[2];
    const float* qW = (const float*)d_in[3];
    const float* kW = (const float*)d_in[4];
    const float* vW = (const float*)d_in[5];

    int N  = in_sizes[0] / (49 * 64);
    int Cv = in_sizes[2] / (N * 49);

    static bool attr_done = false;
    if (!attr_done) {
        cudaFuncSetAttribute(ax_pv,
                             cudaFuncAttributeMaxDynamicSharedMemorySize,
                             SMEMB_BYTES);
        attr_done = true;
    }

    dim3 ga(N, 2);
    ax_logits<<<ga, 384>>>(qH, kH, qW, kW);

    dim3 gb((Cv + CHUNK - 1) / CHUNK, N);
    ax_pv<<<gb, 256, SMEMB_BYTES>>>(vH, vW, (float*)d_out, Cv);
}